// round 16
// baseline (speedup 1.0000x reference)
#include <cuda_runtime.h>
#include <cstdint>

// DigitCaps dynamic routing, fused.
// b_t[i,j] = u_hat[b,i,j,:] . Vsum_t[b,j,:], Vsum_t = sum_{tau<t} v_tau
// W prepacked [chunk6][g][e][dpair][j]; cp.async.bulk staging, 3-slot ring.
// FIRST: G=6 chunks, ISPLITS=8, 2 blocks/SM, 4 batches/thread.
// non-FIRST: G=12 chunks, ISPLITS=32 (3 double-chunks/block, 1024 blocks)
//            for wave balance; 1 block/SM, 4 batches/thread.

#define B_      512
#define NI      1152
#define NJ      10
#define DI      8
#define DO      16

#define THREADS 256
#define BTF     16
#define G_      6
#define ISPLITS 8                   // FIRST
#define ICHUNK  144
#define NCHUNK  24                  // FIRST: 6-i chunks per split
#define ISPLITS2 32                 // non-FIRST
#define NCHUNK2  3                  // non-FIRST: 12-i chunks per split
#define NCHUNK_TOTAL (ISPLITS * NCHUNK)
#define NPART_F 8
#define NPART_S 32

#define WTILE_ULL  644
#define WBUF_ULL   (G_ * WTILE_ULL)
#define WBUF       (WBUF_ULL * 2)
#define NBUF    3
#define VROW    18
#define CHUNK_BYTES  (WBUF * 4)           // 30912  (G=6)
#define CHUNK2_BYTES (2 * WBUF * 4)       // 61824  (G=12)

#define MBAR_OFF_F  (NBUF * WBUF + BTF * NJ * VROW)
#define SMEM_F      ((MBAR_OFF_F + 8) * 4)
#define MBAR_OFF_S  (NBUF * 2 * WBUF + BTF * NJ * VROW)
#define SMEM_S      ((MBAR_OFF_S + 8) * 4)

__device__ float g_wpad[(size_t)NCHUNK_TOTAL * WBUF];
__device__ float g_partial8[(size_t)B_ * NPART_F * NJ * DO];
__device__ float g_partial32[(size_t)B_ * NPART_S * NJ * DO];
__device__ float g_vsum[B_ * NJ * DO];

using ull = unsigned long long;

__device__ __forceinline__ ull fma2(ull a, ull b, ull c) {
    ull d; asm("fma.rn.f32x2 %0, %1, %2, %3;" : "=l"(d) : "l"(a), "l"(b), "l"(c)); return d;
}
__device__ __forceinline__ ull add2(ull a, ull b) {
    ull d; asm("add.rn.f32x2 %0, %1, %2;" : "=l"(d) : "l"(a), "l"(b)); return d;
}
__device__ __forceinline__ ull bcast2(float x) {
    ull d; asm("mov.b64 %0, {%1, %1};" : "=l"(d) : "f"(x)); return d;
}
__device__ __forceinline__ ull pack2(float x, float y) {
    ull d; asm("mov.b64 %0, {%1, %2};" : "=l"(d) : "f"(x), "f"(y)); return d;
}
__device__ __forceinline__ float sum2(ull a) {
    float l, h; asm("mov.b64 {%0, %1}, %2;" : "=f"(l), "=f"(h) : "l"(a)); return l + h;
}
__device__ __forceinline__ void st2(float* p, ull v) { *(ull*)p = v; }

__device__ __forceinline__ void mbar_init(uint32_t addr, uint32_t count) {
    asm volatile("mbarrier.init.shared.b64 [%0], %1;" :: "r"(addr), "r"(count) : "memory");
}
__device__ __forceinline__ void mbar_wait(uint32_t addr, uint32_t parity) {
    asm volatile(
        "{\n\t.reg .pred P;\n\t"
        "WL_%=:\n\t"
        "mbarrier.try_wait.parity.acquire.cta.shared::cta.b64 P, [%0], %1, 0x989680;\n\t"
        "@P bra.uni WD_%=;\n\t"
        "bra.uni WL_%=;\n\t"
        "WD_%=:\n\t}"
        :: "r"(addr), "r"(parity) : "memory");
}

__device__ __forceinline__ void issue_bulk(const float* src, uint32_t dst,
                                           uint32_t bytes, uint32_t mbar) {
    asm volatile("mbarrier.arrive.expect_tx.shared.b64 _, [%0], %1;"
                 :: "r"(mbar), "r"(bytes) : "memory");
    asm volatile(
        "cp.async.bulk.shared::cluster.global.mbarrier::complete_tx::bytes "
        "[%0], [%1], %2, [%3];"
        :: "r"(dst), "l"(src), "r"(bytes), "r"(mbar) : "memory");
}

// W[i][j][e][d] -> g_wpad ull[chunk*WBUF_ULL + g*644 + e*80 + k*10 + j]
__global__ void prepack_kernel(const float* __restrict__ W) {
    int t = blockIdx.x * blockDim.x + threadIdx.x;
    if (t >= NI * NJ * DI) return;
    int e = t % DI;
    int r = t / DI;
    int j = r % NJ;
    int i = r / NJ;
    int chunk = i / G_;
    int g = i - chunk * G_;
    const float4* src = (const float4*)(W + (((size_t)(i * NJ + j)) * DI + e) * DO);
    float4 v0 = src[0], v1 = src[1], v2 = src[2], v3 = src[3];
    ull* dst = (ull*)g_wpad + (size_t)chunk * WBUF_ULL + g * WTILE_ULL + e * 80 + j;
    dst[0]  = pack2(v0.x, v0.y);
    dst[10] = pack2(v0.z, v0.w);
    dst[20] = pack2(v1.x, v1.y);
    dst[30] = pack2(v1.z, v1.w);
    dst[40] = pack2(v2.x, v2.y);
    dst[50] = pack2(v2.z, v2.w);
    dst[60] = pack2(v3.x, v3.y);
    dst[70] = pack2(v3.z, v3.w);
}

// ---------------- FIRST: uniform c=0.1, 4 batches/thread, G=6 ----------------
__global__ void __launch_bounds__(THREADS, 2)
sweep_first_kernel(const float* __restrict__ u) {
    extern __shared__ float smem[];
    float* wst = smem;
    float* red = smem;

    const int tid  = threadIdx.x;
    const int lane = tid & 31;
    const int warp = tid >> 5;
    const int seg  = lane / 10;
    const bool active = (seg < 3);
    const int j    = lane - seg * 10;
    const int unit = warp * 3 + (active ? seg : 0);
    const int bq   = unit & 3;
    const int g    = unit >> 2;

    const int c0g   = blockIdx.x * NCHUNK;
    const int i0    = blockIdx.x * ICHUNK;
    const int bbase = blockIdx.y * BTF;

    uint32_t smem_base = (uint32_t)__cvta_generic_to_shared(wst);
    uint32_t mbar_base = (uint32_t)__cvta_generic_to_shared(smem + MBAR_OFF_F);

    if (tid == 0) {
        mbar_init(mbar_base + 0, 1);
        mbar_init(mbar_base + 8, 1);
        mbar_init(mbar_base + 16, 1);
    }
    __syncthreads();

    if (tid == 0) {
        issue_bulk(g_wpad + (size_t)c0g * WBUF, smem_base, CHUNK_BYTES, mbar_base);
        issue_bulk(g_wpad + (size_t)(c0g + 1) * WBUF, smem_base + WBUF * 4,
                   CHUNK_BYTES, mbar_base + 8);
    }

    ull sacc[4][8];
    #pragma unroll
    for (int b = 0; b < 4; b++)
        #pragma unroll
        for (int k = 0; k < 8; k++) sacc[b][k] = 0ULL;

    const int b0 = bbase + bq * 4;
    const float* up = u + (size_t)b0 * NI * DI;

    for (int c = 0; c < NCHUNK; c++) {
        const int buf = c % NBUF;
        const int i = i0 + c * G_ + g;

        float ur[4][8];
        if (active) {
            #pragma unroll
            for (int b = 0; b < 4; b++) {
                const float4* s = (const float4*)(up + (size_t)b * NI * DI + (size_t)i * DI);
                float4 x = s[0], y = s[1];
                ur[b][0]=x.x; ur[b][1]=x.y; ur[b][2]=x.z; ur[b][3]=x.w;
                ur[b][4]=y.x; ur[b][5]=y.y; ur[b][6]=y.z; ur[b][7]=y.w;
            }
        }

        __syncthreads();
        if (tid == 0 && c + 2 < NCHUNK)
            issue_bulk(g_wpad + (size_t)(c0g + c + 2) * WBUF,
                       smem_base + (uint32_t)(((c + 2) % NBUF) * WBUF) * 4,
                       CHUNK_BYTES, mbar_base + ((c + 2) % NBUF) * 8);

        mbar_wait(mbar_base + buf * 8, (c / NBUF) & 1);

        if (active) {
            const ull* wt = (const ull*)(wst + buf * WBUF) + g * WTILE_ULL + j;
            #pragma unroll
            for (int e = 0; e < 8; e++) {
                const ull* wte = wt + e * 80;
                ull ue0 = bcast2(ur[0][e]);
                ull ue1 = bcast2(ur[1][e]);
                ull ue2 = bcast2(ur[2][e]);
                ull ue3 = bcast2(ur[3][e]);
                #pragma unroll
                for (int k = 0; k < 8; k++) {
                    ull wv = wte[k * 10];
                    sacc[0][k] = fma2(ue0, wv, sacc[0][k]);
                    sacc[1][k] = fma2(ue1, wv, sacc[1][k]);
                    sacc[2][k] = fma2(ue2, wv, sacc[2][k]);
                    sacc[3][k] = fma2(ue3, wv, sacc[3][k]);
                }
            }
        }
    }

    __syncthreads();
    if (active) {
        #pragma unroll
        for (int b = 0; b < 4; b++) {
            int r = ((bq * 4 + b) * 6 + g) * 10 + j;
            #pragma unroll
            for (int k = 0; k < 8; k++)
                st2(red + r * 16 + 2 * k, sacc[b][k]);
        }
    }
    __syncthreads();

    #pragma unroll 1
    for (int idx = tid; idx < BTF * NJ * DO; idx += THREADS) {
        int d  = idx & 15;
        int r  = idx >> 4;
        int jj = r % 10;
        int bt = r / 10;
        float s = 0.f;
        #pragma unroll
        for (int gg = 0; gg < 6; gg++)
            s += red[((bt * 6 + gg) * 10 + jj) * 16 + d];
        s *= 0.1f;
        int b = bbase + bt;
        g_partial8[((size_t)(b * NPART_F + blockIdx.x) * NJ + jj) * DO + d] = s;
    }
}

// shared routing body: one i's worth of a-loop + logit + softmax + sacc update
__device__ __forceinline__ void route_i(
    const ull* __restrict__ wt, const float ur[4][8],
    const float* __restrict__ vsb0, ull sacc[4][8],
    int sl5, int sl1, int sl2, int sl4)
{
    ull a[4][8];
    #pragma unroll
    for (int b = 0; b < 4; b++)
        #pragma unroll
        for (int k = 0; k < 8; k++) a[b][k] = 0ULL;
    #pragma unroll
    for (int e = 0; e < 8; e++) {
        const ull* wte = wt + e * 80;
        ull ue0 = bcast2(ur[0][e]);
        ull ue1 = bcast2(ur[1][e]);
        ull ue2 = bcast2(ur[2][e]);
        ull ue3 = bcast2(ur[3][e]);
        #pragma unroll
        for (int k = 0; k < 8; k++) {
            ull wv = wte[k * 10];
            a[0][k] = fma2(ue0, wv, a[0][k]);
            a[1][k] = fma2(ue1, wv, a[1][k]);
            a[2][k] = fma2(ue2, wv, a[2][k]);
            a[3][k] = fma2(ue3, wv, a[3][k]);
        }
    }

    float ex[4];
    #pragma unroll
    for (int b = 0; b < 4; b++) {
        const ull* vsb = (const ull*)(vsb0 + b * NJ * VROW);
        ull da = 0ULL, db = 0ULL;
        #pragma unroll
        for (int k = 0; k < 4; k++) {
            da = fma2(a[b][k],     vsb[k],     da);
            db = fma2(a[b][k + 4], vsb[k + 4], db);
        }
        ex[b] = __expf(sum2(add2(da, db)));
    }

    const unsigned M = 0x3FFFFFFFu;
    float s5[4], as[4], bs[4], tt[4];
    #pragma unroll
    for (int b = 0; b < 4; b++) s5[b] = ex[b] + __shfl_sync(M, ex[b], sl5);
    #pragma unroll
    for (int b = 0; b < 4; b++) as[b] = s5[b] + __shfl_sync(M, s5[b], sl1);
    #pragma unroll
    for (int b = 0; b < 4; b++) bs[b] = as[b] + __shfl_sync(M, as[b], sl2);
    #pragma unroll
    for (int b = 0; b < 4; b++) tt[b] = bs[b] + __shfl_sync(M, s5[b], sl4);

    #pragma unroll
    for (int b = 0; b < 4; b++) {
        ull cb = bcast2(__fdividef(ex[b], tt[b]));
        #pragma unroll
        for (int k = 0; k < 8; k++)
            sacc[b][k] = fma2(cb, a[b][k], sacc[b][k]);
    }
}

// ---- non-FIRST: 4 batches/thread, G=12, ISPLITS2=32 (3 double-chunks/block) ----
__global__ void __launch_bounds__(THREADS, 1)
sweep_kernel(const float* __restrict__ u) {
    extern __shared__ float smem[];
    float* wst = smem;
    float* vsm = smem + NBUF * 2 * WBUF;
    float* red = smem;

    const int tid  = threadIdx.x;
    const int lane = tid & 31;
    const int warp = tid >> 5;
    const int seg  = lane / 10;
    const bool active = (seg < 3);
    const int j    = lane - seg * 10;
    const int unit = warp * 3 + (active ? seg : 0);
    const int bq   = unit & 3;
    const int g    = unit >> 2;

    const int base = seg * 10;
    const int sl5 = base + (j >= 5 ? j - 5 : j + 5);
    const int sl1 = base + (j >= 9 ? j - 9 : j + 1);
    const int sl2 = base + (j >= 8 ? j - 8 : j + 2);
    const int sl4 = base + (j >= 6 ? j - 6 : j + 4);

    const int dc0   = blockIdx.x * NCHUNK2;   // global double-chunk base
    const int i0    = blockIdx.x * (NCHUNK2 * 12);   // 36 i's per block
    const int bbase = blockIdx.y * BTF;

    uint32_t smem_base = (uint32_t)__cvta_generic_to_shared(wst);
    uint32_t mbar_base = (uint32_t)__cvta_generic_to_shared(smem + MBAR_OFF_S);

    if (tid == 0) {
        mbar_init(mbar_base + 0, 1);
        mbar_init(mbar_base + 8, 1);
        mbar_init(mbar_base + 16, 1);
    }
    __syncthreads();

    // issue ring prefills FIRST so TMA latency overlaps vsum staging
    if (tid == 0) {
        issue_bulk(g_wpad + (size_t)dc0 * 2 * WBUF, smem_base, CHUNK2_BYTES, mbar_base);
        issue_bulk(g_wpad + (size_t)(dc0 + 1) * 2 * WBUF, smem_base + 2 * WBUF * 4,
                   CHUNK2_BYTES, mbar_base + 8);
    }

    for (int idx = tid; idx < BTF * NJ * DO; idx += THREADS) {
        vsm[(idx >> 4) * VROW + (idx & 15)] = g_vsum[bbase * NJ * DO + idx];
    }

    ull sacc[4][8];
    #pragma unroll
    for (int b = 0; b < 4; b++)
        #pragma unroll
        for (int k = 0; k < 8; k++) sacc[b][k] = 0ULL;

    const int b0 = bbase + bq * 4;
    const float* up = u + (size_t)b0 * NI * DI;
    const float* vsb0 = vsm + ((bq * 4) * NJ + j) * VROW;

    for (int c = 0; c < NCHUNK2; c++) {
        const int buf = c % NBUF;
        const int ia = i0 + c * 12 + g;
        const int ib = ia + 6;

        float ur[4][8];
        if (active) {
            #pragma unroll
            for (int b = 0; b < 4; b++) {
                const float4* s = (const float4*)(up + (size_t)b * NI * DI + (size_t)ia * DI);
                float4 x = s[0], y = s[1];
                ur[b][0]=x.x; ur[b][1]=x.y; ur[b][2]=x.z; ur[b][3]=x.w;
                ur[b][4]=y.x; ur[b][5]=y.y; ur[b][6]=y.z; ur[b][7]=y.w;
            }
        }

        __syncthreads();   // vsum staged (c=0) / slot reusable (c>0)
        if (tid == 0 && c + 2 < NCHUNK2)
            issue_bulk(g_wpad + (size_t)(dc0 + c + 2) * 2 * WBUF,
                       smem_base + (uint32_t)(((c + 2) % NBUF) * 2 * WBUF) * 4,
                       CHUNK2_BYTES, mbar_base + ((c + 2) % NBUF) * 8);

        mbar_wait(mbar_base + buf * 8, 0);   // c < 3, parity always 0

        if (active) {
            const ull* slot = (const ull*)(wst + buf * 2 * WBUF);
            route_i(slot + g * WTILE_ULL + j, ur, vsb0, sacc, sl5, sl1, sl2, sl4);
            #pragma unroll
            for (int b = 0; b < 4; b++) {
                const float4* s = (const float4*)(up + (size_t)b * NI * DI + (size_t)ib * DI);
                float4 x = s[0], y = s[1];
                ur[b][0]=x.x; ur[b][1]=x.y; ur[b][2]=x.z; ur[b][3]=x.w;
                ur[b][4]=y.x; ur[b][5]=y.y; ur[b][6]=y.z; ur[b][7]=y.w;
            }
            route_i(slot + WBUF_ULL + g * WTILE_ULL + j, ur, vsb0, sacc, sl5, sl1, sl2, sl4);
        }
    }

    // ---- in-block reduction over g ----
    __syncthreads();
    if (active) {
        #pragma unroll
        for (int b = 0; b < 4; b++) {
            int r = ((bq * 4 + b) * 6 + g) * 10 + j;
            #pragma unroll
            for (int k = 0; k < 8; k++)
                st2(red + r * 16 + 2 * k, sacc[b][k]);
        }
    }
    __syncthreads();

    #pragma unroll 1
    for (int idx = tid; idx < BTF * NJ * DO; idx += THREADS) {
        int d  = idx & 15;
        int r  = idx >> 4;
        int jj = r % 10;
        int bt = r / 10;
        float s = 0.f;
        #pragma unroll
        for (int gg = 0; gg < 6; gg++)
            s += red[((bt * 6 + gg) * 10 + jj) * 16 + d];
        int b = bbase + bt;
        g_partial32[((size_t)(b * NPART_S + blockIdx.x) * NJ + jj) * DO + d] = s;
    }
}

template <bool FIRST, bool LAST>
__global__ void reduce_kernel(float* __restrict__ out) {
    int t = blockIdx.x * blockDim.x + threadIdx.x;
    if (t >= B_ * NJ * 4) return;
    int q = t & 3;
    int j = (t >> 2) % NJ;
    int b = t / (NJ * 4);

    const int NP = FIRST ? NPART_F : NPART_S;
    const float4* src = (const float4*)(FIRST ? g_partial8 : g_partial32)
                        + ((size_t)(b * NP) * NJ + j) * 4 + q;
    float4 acc = make_float4(0.f, 0.f, 0.f, 0.f);
    #pragma unroll 8
    for (int p = 0; p < NP; p++) {
        float4 x = src[(size_t)p * NJ * 4];
        acc.x += x.x; acc.y += x.y; acc.z += x.z; acc.w += x.w;
    }

    float sq = acc.x * acc.x + acc.y * acc.y + acc.z * acc.z + acc.w * acc.w;
    sq += __shfl_xor_sync(0xFFFFFFFFu, sq, 1);
    sq += __shfl_xor_sync(0xFFFFFFFFu, sq, 2);
    float norm = sqrtf(sq);
    float factor = sq / (norm * (1.f + sq));

    float4 v = make_float4(factor * acc.x, factor * acc.y, factor * acc.z, factor * acc.w);
    if (LAST) {
        ((float4*)out)[(size_t)(b * NJ + j) * 4 + q] = v;
    } else {
        float4* vp = (float4*)g_vsum + (b * NJ + j) * 4 + q;
        if (FIRST) {
            *vp = v;
        } else {
            float4 o = *vp;
            *vp = make_float4(o.x + v.x, o.y + v.y, o.z + v.z, o.w + v.w);
        }
    }
}

extern "C" void kernel_launch(void* const* d_in, const int* in_sizes, int n_in,
                              void* d_out, int out_size) {
    const float* u = (const float*)d_in[0];
    const float* W = (const float*)d_in[1];
    float* out = (float*)d_out;

    cudaFuncSetAttribute(sweep_first_kernel, cudaFuncAttributeMaxDynamicSharedMemorySize, SMEM_F);
    cudaFuncSetAttribute(sweep_kernel,       cudaFuncAttributeMaxDynamicSharedMemorySize, SMEM_S);

    dim3 gridF(ISPLITS, B_ / BTF);                           // 8 x 32
    dim3 gridS(ISPLITS2, B_ / BTF);                          // 32 x 32 = 1024 blocks
    const int rblocks = (B_ * NJ * 4 + 255) / 256;           // 80
    const int pthreads = NI * NJ * DI;
    const int pblocks = (pthreads + 255) / 256;

    prepack_kernel<<<pblocks, 256>>>(W);                      // 0
    sweep_first_kernel<<<gridF, THREADS, SMEM_F>>>(u);        // 1
    reduce_kernel<true, false><<<rblocks, 256>>>(out);        // 2
    sweep_kernel<<<gridS, THREADS, SMEM_S>>>(u);              // 3
    reduce_kernel<false, false><<<rblocks, 256>>>(out);       // 4
    sweep_kernel<<<gridS, THREADS, SMEM_S>>>(u);              // 5  <- ncu -s 5
    reduce_kernel<false, true><<<rblocks, 256>>>(out);        // 6
}

// round 17
// speedup vs baseline: 1.1977x; 1.1977x over previous
#include <cuda_runtime.h>
#include <cstdint>

// DigitCaps dynamic routing, fused.
// b_t[i,j] = u_hat[b,i,j,:] . Vsum_t[b,j,:], Vsum_t = sum_{tau<t} v_tau
// W prepacked [chunk6][g][e][dpair][j]; cp.async.bulk staging, 3-slot ring.
// FIRST: G=6, ISPLITS=8, 2 blocks/SM, 4 batches/thread -> partials1 (x0.1).
// route<ITER>: G=12, ISPLITS=8, 1 block/SM, 4 batches/thread; computes its own
//   Vsum in the prologue from partial buffers (squash fused, reduces removed).
// Final reduce only for the output.

#define B_      512
#define NI      1152
#define NJ      10
#define DI      8
#define DO      16

#define THREADS 256
#define BTF     16
#define G_      6
#define ISPLITS 8
#define ICHUNK  144
#define NCHUNK  24                  // FIRST: 6-i chunks per split
#define NCHUNK2 12                  // route: 12-i chunks per split
#define NCHUNK_TOTAL (ISPLITS * NCHUNK)
#define NPART   8

#define WTILE_ULL  644
#define WBUF_ULL   (G_ * WTILE_ULL)
#define WBUF       (WBUF_ULL * 2)
#define NBUF    3
#define VROW    18
#define CHUNK_BYTES  (WBUF * 4)           // 30912  (G=6)
#define CHUNK2_BYTES (2 * WBUF * 4)       // 61824  (G=12)

#define MBAR_OFF_F  (NBUF * WBUF + BTF * NJ * VROW)
#define SMEM_F      ((MBAR_OFF_F + 8) * 4)
#define MBAR_OFF_S  (NBUF * 2 * WBUF + BTF * NJ * VROW)
#define SMEM_S      ((MBAR_OFF_S + 8) * 4)

__device__ float g_wpad[(size_t)NCHUNK_TOTAL * WBUF];
__device__ float g_p1[(size_t)B_ * NPART * NJ * DO];
__device__ float g_p2[(size_t)B_ * NPART * NJ * DO];
__device__ float g_p3[(size_t)B_ * NPART * NJ * DO];

using ull = unsigned long long;

__device__ __forceinline__ ull fma2(ull a, ull b, ull c) {
    ull d; asm("fma.rn.f32x2 %0, %1, %2, %3;" : "=l"(d) : "l"(a), "l"(b), "l"(c)); return d;
}
__device__ __forceinline__ ull add2(ull a, ull b) {
    ull d; asm("add.rn.f32x2 %0, %1, %2;" : "=l"(d) : "l"(a), "l"(b)); return d;
}
__device__ __forceinline__ ull bcast2(float x) {
    ull d; asm("mov.b64 %0, {%1, %1};" : "=l"(d) : "f"(x)); return d;
}
__device__ __forceinline__ ull pack2(float x, float y) {
    ull d; asm("mov.b64 %0, {%1, %2};" : "=l"(d) : "f"(x), "f"(y)); return d;
}
__device__ __forceinline__ float sum2(ull a) {
    float l, h; asm("mov.b64 {%0, %1}, %2;" : "=f"(l), "=f"(h) : "l"(a)); return l + h;
}
__device__ __forceinline__ void st2(float* p, ull v) { *(ull*)p = v; }

__device__ __forceinline__ void mbar_init(uint32_t addr, uint32_t count) {
    asm volatile("mbarrier.init.shared.b64 [%0], %1;" :: "r"(addr), "r"(count) : "memory");
}
__device__ __forceinline__ void mbar_wait(uint32_t addr, uint32_t parity) {
    asm volatile(
        "{\n\t.reg .pred P;\n\t"
        "WL_%=:\n\t"
        "mbarrier.try_wait.parity.acquire.cta.shared::cta.b64 P, [%0], %1, 0x989680;\n\t"
        "@P bra.uni WD_%=;\n\t"
        "bra.uni WL_%=;\n\t"
        "WD_%=:\n\t}"
        :: "r"(addr), "r"(parity) : "memory");
}

__device__ __forceinline__ void issue_bulk(const float* src, uint32_t dst,
                                           uint32_t bytes, uint32_t mbar) {
    asm volatile("mbarrier.arrive.expect_tx.shared.b64 _, [%0], %1;"
                 :: "r"(mbar), "r"(bytes) : "memory");
    asm volatile(
        "cp.async.bulk.shared::cluster.global.mbarrier::complete_tx::bytes "
        "[%0], [%1], %2, [%3];"
        :: "r"(dst), "l"(src), "r"(bytes), "r"(mbar) : "memory");
}

// squash(sum_p partials[p]) for one (b,j): returns v[16] in vout
__device__ __forceinline__ void squash_row(const float* __restrict__ part,
                                           size_t b, int j, float* vout) {
    float acc[16];
    #pragma unroll
    for (int d = 0; d < 16; d++) acc[d] = 0.f;
    const float4* src = (const float4*)part + ((b * NPART) * NJ + j) * 4;
    #pragma unroll
    for (int p = 0; p < NPART; p++) {
        float4 x0 = src[(size_t)p * NJ * 4 + 0];
        float4 x1 = src[(size_t)p * NJ * 4 + 1];
        float4 x2 = src[(size_t)p * NJ * 4 + 2];
        float4 x3 = src[(size_t)p * NJ * 4 + 3];
        acc[0]+=x0.x; acc[1]+=x0.y; acc[2]+=x0.z; acc[3]+=x0.w;
        acc[4]+=x1.x; acc[5]+=x1.y; acc[6]+=x1.z; acc[7]+=x1.w;
        acc[8]+=x2.x; acc[9]+=x2.y; acc[10]+=x2.z; acc[11]+=x2.w;
        acc[12]+=x3.x; acc[13]+=x3.y; acc[14]+=x3.z; acc[15]+=x3.w;
    }
    float sq = 0.f;
    #pragma unroll
    for (int d = 0; d < 16; d++) sq += acc[d] * acc[d];
    float norm = sqrtf(sq);
    float factor = sq / (norm * (1.f + sq));
    #pragma unroll
    for (int d = 0; d < 16; d++) vout[d] = factor * acc[d];
}

// W[i][j][e][d] -> g_wpad ull[chunk*WBUF_ULL + g*644 + e*80 + k*10 + j]
__global__ void prepack_kernel(const float* __restrict__ W) {
    int t = blockIdx.x * blockDim.x + threadIdx.x;
    if (t >= NI * NJ * DI) return;
    int e = t % DI;
    int r = t / DI;
    int j = r % NJ;
    int i = r / NJ;
    int chunk = i / G_;
    int g = i - chunk * G_;
    const float4* src = (const float4*)(W + (((size_t)(i * NJ + j)) * DI + e) * DO);
    float4 v0 = src[0], v1 = src[1], v2 = src[2], v3 = src[3];
    ull* dst = (ull*)g_wpad + (size_t)chunk * WBUF_ULL + g * WTILE_ULL + e * 80 + j;
    dst[0]  = pack2(v0.x, v0.y);
    dst[10] = pack2(v0.z, v0.w);
    dst[20] = pack2(v1.x, v1.y);
    dst[30] = pack2(v1.z, v1.w);
    dst[40] = pack2(v2.x, v2.y);
    dst[50] = pack2(v2.z, v2.w);
    dst[60] = pack2(v3.x, v3.y);
    dst[70] = pack2(v3.z, v3.w);
}

// ---------------- FIRST: uniform c=0.1, 4 batches/thread, G=6 ----------------
__global__ void __launch_bounds__(THREADS, 2)
sweep_first_kernel(const float* __restrict__ u) {
    extern __shared__ float smem[];
    float* wst = smem;
    float* red = smem;

    const int tid  = threadIdx.x;
    const int lane = tid & 31;
    const int warp = tid >> 5;
    const int seg  = lane / 10;
    const bool active = (seg < 3);
    const int j    = lane - seg * 10;
    const int unit = warp * 3 + (active ? seg : 0);
    const int bq   = unit & 3;
    const int g    = unit >> 2;

    const int c0g   = blockIdx.x * NCHUNK;
    const int i0    = blockIdx.x * ICHUNK;
    const int bbase = blockIdx.y * BTF;

    uint32_t smem_base = (uint32_t)__cvta_generic_to_shared(wst);
    uint32_t mbar_base = (uint32_t)__cvta_generic_to_shared(smem + MBAR_OFF_F);

    if (tid == 0) {
        mbar_init(mbar_base + 0, 1);
        mbar_init(mbar_base + 8, 1);
        mbar_init(mbar_base + 16, 1);
    }
    __syncthreads();

    if (tid == 0) {
        issue_bulk(g_wpad + (size_t)c0g * WBUF, smem_base, CHUNK_BYTES, mbar_base);
        issue_bulk(g_wpad + (size_t)(c0g + 1) * WBUF, smem_base + WBUF * 4,
                   CHUNK_BYTES, mbar_base + 8);
    }

    ull sacc[4][8];
    #pragma unroll
    for (int b = 0; b < 4; b++)
        #pragma unroll
        for (int k = 0; k < 8; k++) sacc[b][k] = 0ULL;

    const int b0 = bbase + bq * 4;
    const float* up = u + (size_t)b0 * NI * DI;

    for (int c = 0; c < NCHUNK; c++) {
        const int buf = c % NBUF;
        const int i = i0 + c * G_ + g;

        float ur[4][8];
        if (active) {
            #pragma unroll
            for (int b = 0; b < 4; b++) {
                const float4* s = (const float4*)(up + (size_t)b * NI * DI + (size_t)i * DI);
                float4 x = s[0], y = s[1];
                ur[b][0]=x.x; ur[b][1]=x.y; ur[b][2]=x.z; ur[b][3]=x.w;
                ur[b][4]=y.x; ur[b][5]=y.y; ur[b][6]=y.z; ur[b][7]=y.w;
            }
        }

        __syncthreads();
        if (tid == 0 && c + 2 < NCHUNK)
            issue_bulk(g_wpad + (size_t)(c0g + c + 2) * WBUF,
                       smem_base + (uint32_t)(((c + 2) % NBUF) * WBUF) * 4,
                       CHUNK_BYTES, mbar_base + ((c + 2) % NBUF) * 8);

        mbar_wait(mbar_base + buf * 8, (c / NBUF) & 1);

        if (active) {
            const ull* wt = (const ull*)(wst + buf * WBUF) + g * WTILE_ULL + j;
            #pragma unroll
            for (int e = 0; e < 8; e++) {
                const ull* wte = wt + e * 80;
                ull ue0 = bcast2(ur[0][e]);
                ull ue1 = bcast2(ur[1][e]);
                ull ue2 = bcast2(ur[2][e]);
                ull ue3 = bcast2(ur[3][e]);
                #pragma unroll
                for (int k = 0; k < 8; k++) {
                    ull wv = wte[k * 10];
                    sacc[0][k] = fma2(ue0, wv, sacc[0][k]);
                    sacc[1][k] = fma2(ue1, wv, sacc[1][k]);
                    sacc[2][k] = fma2(ue2, wv, sacc[2][k]);
                    sacc[3][k] = fma2(ue3, wv, sacc[3][k]);
                }
            }
        }
    }

    __syncthreads();
    if (active) {
        #pragma unroll
        for (int b = 0; b < 4; b++) {
            int r = ((bq * 4 + b) * 6 + g) * 10 + j;
            #pragma unroll
            for (int k = 0; k < 8; k++)
                st2(red + r * 16 + 2 * k, sacc[b][k]);
        }
    }
    __syncthreads();

    #pragma unroll 1
    for (int idx = tid; idx < BTF * NJ * DO; idx += THREADS) {
        int d  = idx & 15;
        int r  = idx >> 4;
        int jj = r % 10;
        int bt = r / 10;
        float s = 0.f;
        #pragma unroll
        for (int gg = 0; gg < 6; gg++)
            s += red[((bt * 6 + gg) * 10 + jj) * 16 + d];
        s *= 0.1f;
        int b = bbase + bt;
        g_p1[((size_t)(b * NPART + blockIdx.x) * NJ + jj) * DO + d] = s;
    }
}

// shared routing body: one i's worth of a-loop + logit + softmax + sacc update
__device__ __forceinline__ void route_i(
    const ull* __restrict__ wt, const float ur[4][8],
    const float* __restrict__ vsb0, ull sacc[4][8],
    int sl5, int sl1, int sl2, int sl4)
{
    ull a[4][8];
    #pragma unroll
    for (int b = 0; b < 4; b++)
        #pragma unroll
        for (int k = 0; k < 8; k++) a[b][k] = 0ULL;
    #pragma unroll
    for (int e = 0; e < 8; e++) {
        const ull* wte = wt + e * 80;
        ull ue0 = bcast2(ur[0][e]);
        ull ue1 = bcast2(ur[1][e]);
        ull ue2 = bcast2(ur[2][e]);
        ull ue3 = bcast2(ur[3][e]);
        #pragma unroll
        for (int k = 0; k < 8; k++) {
            ull wv = wte[k * 10];
            a[0][k] = fma2(ue0, wv, a[0][k]);
            a[1][k] = fma2(ue1, wv, a[1][k]);
            a[2][k] = fma2(ue2, wv, a[2][k]);
            a[3][k] = fma2(ue3, wv, a[3][k]);
        }
    }

    float ex[4];
    #pragma unroll
    for (int b = 0; b < 4; b++) {
        const ull* vsb = (const ull*)(vsb0 + b * NJ * VROW);
        ull da = 0ULL, db = 0ULL;
        #pragma unroll
        for (int k = 0; k < 4; k++) {
            da = fma2(a[b][k],     vsb[k],     da);
            db = fma2(a[b][k + 4], vsb[k + 4], db);
        }
        ex[b] = __expf(sum2(add2(da, db)));
    }

    const unsigned M = 0x3FFFFFFFu;
    float s5[4], as[4], bs[4], tt[4];
    #pragma unroll
    for (int b = 0; b < 4; b++) s5[b] = ex[b] + __shfl_sync(M, ex[b], sl5);
    #pragma unroll
    for (int b = 0; b < 4; b++) as[b] = s5[b] + __shfl_sync(M, s5[b], sl1);
    #pragma unroll
    for (int b = 0; b < 4; b++) bs[b] = as[b] + __shfl_sync(M, as[b], sl2);
    #pragma unroll
    for (int b = 0; b < 4; b++) tt[b] = bs[b] + __shfl_sync(M, s5[b], sl4);

    #pragma unroll
    for (int b = 0; b < 4; b++) {
        ull cb = bcast2(__fdividef(ex[b], tt[b]));
        #pragma unroll
        for (int k = 0; k < 8; k++)
            sacc[b][k] = fma2(cb, a[b][k], sacc[b][k]);
    }
}

// ---- routing sweep (ITER=2 or 3): 4 batches/thread, G=12, fused vsum prologue ----
template <int ITER>
__global__ void __launch_bounds__(THREADS, 1)
sweep_route_kernel(const float* __restrict__ u) {
    extern __shared__ float smem[];
    float* wst = smem;
    float* vsm = smem + NBUF * 2 * WBUF;
    float* red = smem;

    const int tid  = threadIdx.x;
    const int lane = tid & 31;
    const int warp = tid >> 5;
    const int seg  = lane / 10;
    const bool active = (seg < 3);
    const int j    = lane - seg * 10;
    const int unit = warp * 3 + (active ? seg : 0);
    const int bq   = unit & 3;
    const int g    = unit >> 2;

    const int base = seg * 10;
    const int sl5 = base + (j >= 5 ? j - 5 : j + 5);
    const int sl1 = base + (j >= 9 ? j - 9 : j + 1);
    const int sl2 = base + (j >= 8 ? j - 8 : j + 2);
    const int sl4 = base + (j >= 6 ? j - 6 : j + 4);

    const int dc0   = blockIdx.x * NCHUNK2;
    const int i0    = blockIdx.x * ICHUNK;
    const int bbase = blockIdx.y * BTF;

    uint32_t smem_base = (uint32_t)__cvta_generic_to_shared(wst);
    uint32_t mbar_base = (uint32_t)__cvta_generic_to_shared(smem + MBAR_OFF_S);

    if (tid == 0) {
        mbar_init(mbar_base + 0, 1);
        mbar_init(mbar_base + 8, 1);
        mbar_init(mbar_base + 16, 1);
    }
    __syncthreads();

    // TMA ring prefill first: latency overlaps the vsum squash below
    if (tid == 0) {
        issue_bulk(g_wpad + (size_t)dc0 * 2 * WBUF, smem_base, CHUNK2_BYTES, mbar_base);
        issue_bulk(g_wpad + (size_t)(dc0 + 1) * 2 * WBUF, smem_base + 2 * WBUF * 4,
                   CHUNK2_BYTES, mbar_base + 8);
    }

    // fused vsum: v1 (+ v2 for ITER 3), one (b,j) per thread
    for (int t = tid; t < BTF * NJ; t += THREADS) {
        int bt = t / NJ;
        int jj = t - bt * NJ;
        size_t b = (size_t)(bbase + bt);
        float v[16];
        squash_row(g_p1, b, jj, v);
        if (ITER == 3) {
            float v2[16];
            squash_row(g_p2, b, jj, v2);
            #pragma unroll
            for (int d = 0; d < 16; d++) v[d] += v2[d];
        }
        float* dst = vsm + (bt * NJ + jj) * VROW;
        #pragma unroll
        for (int d = 0; d < 16; d++) dst[d] = v[d];
    }

    ull sacc[4][8];
    #pragma unroll
    for (int b = 0; b < 4; b++)
        #pragma unroll
        for (int k = 0; k < 8; k++) sacc[b][k] = 0ULL;

    const int b0 = bbase + bq * 4;
    const float* up = u + (size_t)b0 * NI * DI;
    const float* vsb0 = vsm + ((bq * 4) * NJ + j) * VROW;

    for (int c = 0; c < NCHUNK2; c++) {
        const int buf = c % NBUF;
        const int ia = i0 + c * 12 + g;
        const int ib = ia + 6;

        float ur[4][8];
        if (active) {
            #pragma unroll
            for (int b = 0; b < 4; b++) {
                const float4* s = (const float4*)(up + (size_t)b * NI * DI + (size_t)ia * DI);
                float4 x = s[0], y = s[1];
                ur[b][0]=x.x; ur[b][1]=x.y; ur[b][2]=x.z; ur[b][3]=x.w;
                ur[b][4]=y.x; ur[b][5]=y.y; ur[b][6]=y.z; ur[b][7]=y.w;
            }
        }

        __syncthreads();   // vsum staged (c=0) / slot reusable (c>0)
        if (tid == 0 && c + 2 < NCHUNK2)
            issue_bulk(g_wpad + (size_t)(dc0 + c + 2) * 2 * WBUF,
                       smem_base + (uint32_t)(((c + 2) % NBUF) * 2 * WBUF) * 4,
                       CHUNK2_BYTES, mbar_base + ((c + 2) % NBUF) * 8);

        mbar_wait(mbar_base + buf * 8, (c / NBUF) & 1);

        if (active) {
            const ull* slot = (const ull*)(wst + buf * 2 * WBUF);
            route_i(slot + g * WTILE_ULL + j, ur, vsb0, sacc, sl5, sl1, sl2, sl4);
            #pragma unroll
            for (int b = 0; b < 4; b++) {
                const float4* s = (const float4*)(up + (size_t)b * NI * DI + (size_t)ib * DI);
                float4 x = s[0], y = s[1];
                ur[b][0]=x.x; ur[b][1]=x.y; ur[b][2]=x.z; ur[b][3]=x.w;
                ur[b][4]=y.x; ur[b][5]=y.y; ur[b][6]=y.z; ur[b][7]=y.w;
            }
            route_i(slot + WBUF_ULL + g * WTILE_ULL + j, ur, vsb0, sacc, sl5, sl1, sl2, sl4);
        }
    }

    // ---- in-block reduction over g ----
    __syncthreads();
    if (active) {
        #pragma unroll
        for (int b = 0; b < 4; b++) {
            int r = ((bq * 4 + b) * 6 + g) * 10 + j;
            #pragma unroll
            for (int k = 0; k < 8; k++)
                st2(red + r * 16 + 2 * k, sacc[b][k]);
        }
    }
    __syncthreads();

    float* outp = (ITER == 2) ? g_p2 : g_p3;
    #pragma unroll 1
    for (int idx = tid; idx < BTF * NJ * DO; idx += THREADS) {
        int d  = idx & 15;
        int r  = idx >> 4;
        int jj = r % 10;
        int bt = r / 10;
        float s = 0.f;
        #pragma unroll
        for (int gg = 0; gg < 6; gg++)
            s += red[((bt * 6 + gg) * 10 + jj) * 16 + d];
        int b = bbase + bt;
        outp[((size_t)(b * NPART + blockIdx.x) * NJ + jj) * DO + d] = s;
    }
}

// final: out = squash(sum_p g_p3)
__global__ void reduce_last_kernel(float* __restrict__ out) {
    int t = blockIdx.x * blockDim.x + threadIdx.x;
    if (t >= B_ * NJ * 4) return;
    int q = t & 3;
    int j = (t >> 2) % NJ;
    int b = t / (NJ * 4);

    const float4* src = (const float4*)g_p3 + ((size_t)(b * NPART) * NJ + j) * 4 + q;
    float4 acc = make_float4(0.f, 0.f, 0.f, 0.f);
    #pragma unroll
    for (int p = 0; p < NPART; p++) {
        float4 x = src[(size_t)p * NJ * 4];
        acc.x += x.x; acc.y += x.y; acc.z += x.z; acc.w += x.w;
    }

    float sq = acc.x * acc.x + acc.y * acc.y + acc.z * acc.z + acc.w * acc.w;
    sq += __shfl_xor_sync(0xFFFFFFFFu, sq, 1);
    sq += __shfl_xor_sync(0xFFFFFFFFu, sq, 2);
    float norm = sqrtf(sq);
    float factor = sq / (norm * (1.f + sq));

    ((float4*)out)[(size_t)(b * NJ + j) * 4 + q] =
        make_float4(factor * acc.x, factor * acc.y, factor * acc.z, factor * acc.w);
}

extern "C" void kernel_launch(void* const* d_in, const int* in_sizes, int n_in,
                              void* d_out, int out_size) {
    const float* u = (const float*)d_in[0];
    const float* W = (const float*)d_in[1];
    float* out = (float*)d_out;

    cudaFuncSetAttribute(sweep_first_kernel,   cudaFuncAttributeMaxDynamicSharedMemorySize, SMEM_F);
    cudaFuncSetAttribute(sweep_route_kernel<2>, cudaFuncAttributeMaxDynamicSharedMemorySize, SMEM_S);
    cudaFuncSetAttribute(sweep_route_kernel<3>, cudaFuncAttributeMaxDynamicSharedMemorySize, SMEM_S);

    dim3 grid(ISPLITS, B_ / BTF);                            // 8 x 32 = 256 blocks
    const int rblocks = (B_ * NJ * 4 + 255) / 256;           // 80
    const int pthreads = NI * NJ * DI;
    const int pblocks = (pthreads + 255) / 256;

    prepack_kernel<<<pblocks, 256>>>(W);                      // 0
    sweep_first_kernel<<<grid, THREADS, SMEM_F>>>(u);         // 1 -> g_p1
    sweep_route_kernel<2><<<grid, THREADS, SMEM_S>>>(u);      // 2 -> g_p2
    sweep_route_kernel<3><<<grid, THREADS, SMEM_S>>>(u);      // 3 -> g_p3
    reduce_last_kernel<<<rblocks, 256>>>(out);                // 4 -> out
}